// round 4
// baseline (speedup 1.0000x reference)
#include <cuda_runtime.h>
#include <math.h>

#define OUT 7
#define RATIO 2
#define NSAMP 14      // OUT*RATIO per axis
#define C 64
#define NVOX 343      // 7*7*7

__global__ void roi_align_ms3d_kernel(const float* __restrict__ f0,
                                      const float* __restrict__ f1,
                                      const float* __restrict__ f2,
                                      const float* __restrict__ f3,
                                      const float* __restrict__ boxes,
                                      float* __restrict__ out)
{
    const int b = blockIdx.x;
    const int tid = threadIdx.x;

    __shared__ int   s_lo[3][NSAMP];
    __shared__ int   s_hi[3][NSAMP];
    __shared__ float s_w0[3][NSAMP];
    __shared__ float s_w1[3][NSAMP];
    __shared__ int   s_lvl;

    if (tid == 0) {
        float x0 = boxes[b*6+0], y0 = boxes[b*6+1], z0 = boxes[b*6+2];
        float x1 = boxes[b*6+3], y1 = boxes[b*6+4], z1 = boxes[b*6+5];
        float vol = (x1 - x0) * (y1 - y0) * (z1 - z0);
        float s   = cbrtf(vol);
        float lf  = floorf(4.0f + log2f(s / 160.0f) + 1e-6f);
        int   li  = (int)lf;
        li = min(max(li, 2), 5) - 2;
        s_lvl = li;
    }
    __syncthreads();

    const int lvl  = s_lvl;
    const int dim  = 64 >> lvl;
    const float fdim = (float)dim;
    const float scale = fdim / 256.0f;   // 0.25 / 2^lvl

    if (tid < 3 * NSAMP) {
        int axis = tid / NSAMP;
        int j    = tid % NSAMP;
        float b0 = boxes[b*6 + axis]     * scale;
        float b1 = boxes[b*6 + 3 + axis] * scale;
        float size = fmaxf(b1 - b0, 1.0f);
        float bsz  = size / (float)OUT;
        int o = j >> 1, ss = j & 1;
        float offs = (float)o + ((float)ss + 0.5f) * 0.5f;
        float c = b0 + offs * bsz;
        float valid = (c > -1.0f && c < fdim) ? 1.0f : 0.0f;
        float cc = fminf(fmaxf(c, 0.0f), fdim - 1.0f);
        int lo = (int)floorf(cc);
        int hi = min(lo + 1, dim - 1);
        float frac = cc - (float)lo;
        s_lo[axis][j] = lo;
        s_hi[axis][j] = hi;
        s_w0[axis][j] = (1.0f - frac) * valid;
        s_w1[axis][j] = frac * valid;
    }
    __syncthreads();

    const float* feat = (lvl == 0) ? f0 : (lvl == 1) ? f1 : (lvl == 2) ? f2 : f3;
    const long dim1 = dim;
    const long dim2 = (long)dim * dim;
    const long dim3 = dim2 * dim;

    // Each thread handles multiple (channel, voxel) elements; voxel innermost
    // so adjacent lanes read adjacent W coords.
    for (int e = tid; e < C * NVOX; e += blockDim.x) {
        int c = e / NVOX;
        int v = e - c * NVOX;
        int ox = v / 49;
        int rem = v - ox * 49;
        int oy = rem / 7;
        int oz = rem - oy * 7;

        const float* fc = feat + (long)c * dim3;
        float acc = 0.0f;

        #pragma unroll
        for (int sx = 0; sx < 2; sx++) {
            int jx = ox * 2 + sx;
            int lx = s_lo[0][jx], hx = s_hi[0][jx];
            float wx0 = s_w0[0][jx], wx1 = s_w1[0][jx];
            #pragma unroll
            for (int sy = 0; sy < 2; sy++) {
                int jy = oy * 2 + sy;
                int ly = s_lo[1][jy], hy = s_hi[1][jy];
                float wy0 = s_w0[1][jy], wy1 = s_w1[1][jy];

                const float* p00 = fc + (long)lx * dim2 + (long)ly * dim1;
                const float* p01 = fc + (long)lx * dim2 + (long)hy * dim1;
                const float* p10 = fc + (long)hx * dim2 + (long)ly * dim1;
                const float* p11 = fc + (long)hx * dim2 + (long)hy * dim1;

                float w00 = wx0 * wy0, w01 = wx0 * wy1;
                float w10 = wx1 * wy0, w11 = wx1 * wy1;

                #pragma unroll
                for (int sz = 0; sz < 2; sz++) {
                    int jz = oz * 2 + sz;
                    int lz = s_lo[2][jz], hz = s_hi[2][jz];
                    float wz0 = s_w0[2][jz], wz1 = s_w1[2][jz];

                    float v000 = p00[lz], v001 = p00[hz];
                    float v010 = p01[lz], v011 = p01[hz];
                    float v100 = p10[lz], v101 = p10[hz];
                    float v110 = p11[lz], v111 = p11[hz];

                    acc += wz0 * (w00 * v000 + w01 * v010 + w10 * v100 + w11 * v110)
                         + wz1 * (w00 * v001 + w01 * v011 + w10 * v101 + w11 * v111);
                }
            }
        }
        out[((long)b * C + c) * NVOX + v] = acc * 0.125f;
    }
}

extern "C" void kernel_launch(void* const* d_in, const int* in_sizes, int n_in,
                              void* d_out, int out_size)
{
    const float* f0    = (const float*)d_in[0];
    const float* f1    = (const float*)d_in[1];
    const float* f2    = (const float*)d_in[2];
    const float* f3    = (const float*)d_in[3];
    const float* boxes = (const float*)d_in[4];
    float* out = (float*)d_out;

    int nboxes = in_sizes[4] / 6;
    roi_align_ms3d_kernel<<<nboxes, 256>>>(f0, f1, f2, f3, boxes, out);
}

// round 5
// speedup vs baseline: 1.2685x; 1.2685x over previous
#include <cuda_runtime.h>
#include <math.h>

#define OUT 7
#define RATIO 2
#define NSAMP 14      // OUT*RATIO per axis
#define C 64
#define NVOX 343      // 7*7*7
#define CGROUPS 4     // channel-split factor (grid.y)
#define CPG (C / CGROUPS)

__global__ void roi_align_ms3d_kernel(const float* __restrict__ f0,
                                      const float* __restrict__ f1,
                                      const float* __restrict__ f2,
                                      const float* __restrict__ f3,
                                      const float* __restrict__ boxes,
                                      float* __restrict__ out)
{
    const int b   = blockIdx.x;
    const int cg  = blockIdx.y;
    const int tid = threadIdx.x;

    __shared__ int   s_lo[3][NSAMP];
    __shared__ int   s_hi[3][NSAMP];
    __shared__ float s_w0[3][NSAMP];
    __shared__ float s_w1[3][NSAMP];
    __shared__ int   s_lvl;

    if (tid == 0) {
        float x0 = boxes[b*6+0], y0 = boxes[b*6+1], z0 = boxes[b*6+2];
        float x1 = boxes[b*6+3], y1 = boxes[b*6+4], z1 = boxes[b*6+5];
        float vol = (x1 - x0) * (y1 - y0) * (z1 - z0);
        float s   = cbrtf(vol);
        float lf  = floorf(4.0f + log2f(s / 160.0f) + 1e-6f);
        int   li  = (int)lf;
        li = min(max(li, 2), 5) - 2;
        s_lvl = li;
    }
    __syncthreads();

    const int lvl  = s_lvl;
    const int dim  = 64 >> lvl;
    const float fdim = (float)dim;
    const float scale = fdim / 256.0f;   // 0.25 / 2^lvl

    if (tid < 3 * NSAMP) {
        int axis = tid / NSAMP;
        int j    = tid % NSAMP;
        float b0 = boxes[b*6 + axis]     * scale;
        float b1 = boxes[b*6 + 3 + axis] * scale;
        float size = fmaxf(b1 - b0, 1.0f);
        float bsz  = size / (float)OUT;
        int o = j >> 1, ss = j & 1;
        float offs = (float)o + ((float)ss + 0.5f) * 0.5f;
        float c = b0 + offs * bsz;
        float valid = (c > -1.0f && c < fdim) ? 1.0f : 0.0f;
        float cc = fminf(fmaxf(c, 0.0f), fdim - 1.0f);
        int lo = (int)floorf(cc);
        int hi = min(lo + 1, dim - 1);
        float frac = cc - (float)lo;
        s_lo[axis][j] = lo;
        s_hi[axis][j] = hi;
        s_w0[axis][j] = (1.0f - frac) * valid;
        s_w1[axis][j] = frac * valid;
    }
    __syncthreads();

    const float* feat = (lvl == 0) ? f0 : (lvl == 1) ? f1 : (lvl == 2) ? f2 : f3;
    const long dim1 = dim;
    const long dim2 = (long)dim * dim;
    const long dim3 = dim2 * dim;

    const int c_base = cg * CPG;

    // Each thread handles multiple (channel, voxel) elements; voxel innermost
    // so adjacent lanes read adjacent W coords.
    for (int e = tid; e < CPG * NVOX; e += blockDim.x) {
        int cl = e / NVOX;                 // 0..CPG-1
        int v  = e - cl * NVOX;
        int c  = c_base + cl;
        int ox = v / 49;
        int rem = v - ox * 49;
        int oy = rem / 7;
        int oz = rem - oy * 7;

        const float* fc = feat + (long)c * dim3;
        float acc = 0.0f;

        #pragma unroll
        for (int sx = 0; sx < 2; sx++) {
            int jx = ox * 2 + sx;
            int lx = s_lo[0][jx], hx = s_hi[0][jx];
            float wx0 = s_w0[0][jx], wx1 = s_w1[0][jx];
            #pragma unroll
            for (int sy = 0; sy < 2; sy++) {
                int jy = oy * 2 + sy;
                int ly = s_lo[1][jy], hy = s_hi[1][jy];
                float wy0 = s_w0[1][jy], wy1 = s_w1[1][jy];

                const float* p00 = fc + (long)lx * dim2 + (long)ly * dim1;
                const float* p01 = fc + (long)lx * dim2 + (long)hy * dim1;
                const float* p10 = fc + (long)hx * dim2 + (long)ly * dim1;
                const float* p11 = fc + (long)hx * dim2 + (long)hy * dim1;

                float w00 = wx0 * wy0, w01 = wx0 * wy1;
                float w10 = wx1 * wy0, w11 = wx1 * wy1;

                #pragma unroll
                for (int sz = 0; sz < 2; sz++) {
                    int jz = oz * 2 + sz;
                    int lz = s_lo[2][jz], hz = s_hi[2][jz];
                    float wz0 = s_w0[2][jz], wz1 = s_w1[2][jz];

                    float v000 = __ldg(p00 + lz), v001 = __ldg(p00 + hz);
                    float v010 = __ldg(p01 + lz), v011 = __ldg(p01 + hz);
                    float v100 = __ldg(p10 + lz), v101 = __ldg(p10 + hz);
                    float v110 = __ldg(p11 + lz), v111 = __ldg(p11 + hz);

                    acc += wz0 * (w00 * v000 + w01 * v010 + w10 * v100 + w11 * v110)
                         + wz1 * (w00 * v001 + w01 * v011 + w10 * v101 + w11 * v111);
                }
            }
        }
        out[((long)b * C + c) * NVOX + v] = acc * 0.125f;
    }
}

extern "C" void kernel_launch(void* const* d_in, const int* in_sizes, int n_in,
                              void* d_out, int out_size)
{
    const float* f0    = (const float*)d_in[0];
    const float* f1    = (const float*)d_in[1];
    const float* f2    = (const float*)d_in[2];
    const float* f3    = (const float*)d_in[3];
    const float* boxes = (const float*)d_in[4];
    float* out = (float*)d_out;

    int nboxes = in_sizes[4] / 6;
    dim3 grid(nboxes, CGROUPS);
    roi_align_ms3d_kernel<<<grid, 256>>>(f0, f1, f2, f3, boxes, out);
}

// round 6
// speedup vs baseline: 1.5306x; 1.2066x over previous
#include <cuda_runtime.h>
#include <math.h>

#define OUT 7
#define RATIO 2
#define NSAMP 14      // OUT*RATIO per axis
#define C 64
#define NVOX 343      // 7*7*7
#define CGROUPS 8     // channel-split factor (grid.y)
#define CPG (C / CGROUPS)

__global__ __launch_bounds__(256, 4)
void roi_align_ms3d_kernel(const float* __restrict__ f0,
                           const float* __restrict__ f1,
                           const float* __restrict__ f2,
                           const float* __restrict__ f3,
                           const float* __restrict__ boxes,
                           float* __restrict__ out)
{
    const int b   = blockIdx.x;
    const int cg  = blockIdx.y;
    const int tid = threadIdx.x;

    __shared__ int   s_lo[3][NSAMP];
    __shared__ int   s_hi[3][NSAMP];
    __shared__ float s_w0[3][NSAMP];
    __shared__ float s_w1[3][NSAMP];
    __shared__ int   s_lvl;

    if (tid == 0) {
        float x0 = boxes[b*6+0], y0 = boxes[b*6+1], z0 = boxes[b*6+2];
        float x1 = boxes[b*6+3], y1 = boxes[b*6+4], z1 = boxes[b*6+5];
        float vol = (x1 - x0) * (y1 - y0) * (z1 - z0);
        float s   = cbrtf(vol);
        float lf  = floorf(4.0f + log2f(s / 160.0f) + 1e-6f);
        int   li  = (int)lf;
        li = min(max(li, 2), 5) - 2;
        s_lvl = li;
    }
    __syncthreads();

    const int lvl  = s_lvl;
    const int dim  = 64 >> lvl;
    const float fdim = (float)dim;
    const float scale = fdim / 256.0f;   // 0.25 / 2^lvl

    if (tid < 3 * NSAMP) {
        int axis = tid / NSAMP;
        int j    = tid % NSAMP;
        float b0 = boxes[b*6 + axis]     * scale;
        float b1 = boxes[b*6 + 3 + axis] * scale;
        float size = fmaxf(b1 - b0, 1.0f);
        float bsz  = size / (float)OUT;
        int o = j >> 1, ss = j & 1;
        float offs = (float)o + ((float)ss + 0.5f) * 0.5f;
        float c = b0 + offs * bsz;
        float valid = (c > -1.0f && c < fdim) ? 1.0f : 0.0f;
        float cc = fminf(fmaxf(c, 0.0f), fdim - 1.0f);
        int lo = (int)floorf(cc);
        int hi = min(lo + 1, dim - 1);
        float frac = cc - (float)lo;
        s_lo[axis][j] = lo;
        s_hi[axis][j] = hi;
        s_w0[axis][j] = (1.0f - frac) * valid;
        s_w1[axis][j] = frac * valid;
    }
    __syncthreads();

    const float* feat = (lvl == 0) ? f0 : (lvl == 1) ? f1 : (lvl == 2) ? f2 : f3;
    const long dim1 = dim;
    const long dim2 = (long)dim * dim;
    const long dim3 = dim2 * dim;

    const int c_base = cg * CPG;

    // Each thread handles multiple (channel, voxel) elements; voxel innermost
    // so adjacent lanes read adjacent W coords.
    for (int e = tid; e < CPG * NVOX; e += blockDim.x) {
        int cl = e / NVOX;                 // 0..CPG-1
        int v  = e - cl * NVOX;
        int c  = c_base + cl;
        int ox = v / 49;
        int rem = v - ox * 49;
        int oy = rem / 7;
        int oz = rem - oy * 7;

        const float* fc = feat + (long)c * dim3;
        float acc = 0.0f;

        #pragma unroll
        for (int sx = 0; sx < 2; sx++) {
            int jx = ox * 2 + sx;
            int lx = s_lo[0][jx], hx = s_hi[0][jx];
            float wx0 = s_w0[0][jx], wx1 = s_w1[0][jx];
            #pragma unroll
            for (int sy = 0; sy < 2; sy++) {
                int jy = oy * 2 + sy;
                int ly = s_lo[1][jy], hy = s_hi[1][jy];
                float wy0 = s_w0[1][jy], wy1 = s_w1[1][jy];

                const float* p00 = fc + (long)lx * dim2 + (long)ly * dim1;
                const float* p01 = fc + (long)lx * dim2 + (long)hy * dim1;
                const float* p10 = fc + (long)hx * dim2 + (long)ly * dim1;
                const float* p11 = fc + (long)hx * dim2 + (long)hy * dim1;

                float w00 = wx0 * wy0, w01 = wx0 * wy1;
                float w10 = wx1 * wy0, w11 = wx1 * wy1;

                #pragma unroll
                for (int sz = 0; sz < 2; sz++) {
                    int jz = oz * 2 + sz;
                    int lz = s_lo[2][jz], hz = s_hi[2][jz];
                    float wz0 = s_w0[2][jz], wz1 = s_w1[2][jz];

                    float v000 = __ldg(p00 + lz), v001 = __ldg(p00 + hz);
                    float v010 = __ldg(p01 + lz), v011 = __ldg(p01 + hz);
                    float v100 = __ldg(p10 + lz), v101 = __ldg(p10 + hz);
                    float v110 = __ldg(p11 + lz), v111 = __ldg(p11 + hz);

                    acc += wz0 * (w00 * v000 + w01 * v010 + w10 * v100 + w11 * v110)
                         + wz1 * (w00 * v001 + w01 * v011 + w10 * v101 + w11 * v111);
                }
            }
        }
        out[((long)b * C + c) * NVOX + v] = acc * 0.125f;
    }
}

extern "C" void kernel_launch(void* const* d_in, const int* in_sizes, int n_in,
                              void* d_out, int out_size)
{
    const float* f0    = (const float*)d_in[0];
    const float* f1    = (const float*)d_in[1];
    const float* f2    = (const float*)d_in[2];
    const float* f3    = (const float*)d_in[3];
    const float* boxes = (const float*)d_in[4];
    float* out = (float*)d_out;

    int nboxes = in_sizes[4] / 6;
    dim3 grid(nboxes, CGROUPS);
    roi_align_ms3d_kernel<<<grid, 256>>>(f0, f1, f2, f3, boxes, out);
}